// round 4
// baseline (speedup 1.0000x reference)
#include <cuda_runtime.h>
#include <math.h>

#define N_NODES   10000
#define N_EDGES   40000
#define N_GRAPHS  250
#define NODES_PG  40
#define NODE_IN   74
#define EDGE_IN   12
#define H         64
#define C_EF      13
#define C_W       14
#define D2        128
#define RD        1024
#define NB        8       // nodes per proj/gru group
#define TNB       40      // nodes per t block
#define LG        5       // graphs per s2s block

typedef unsigned long long u64;

// ---------------- scratch ---------------------------------------------------
__device__ __align__(16) float g_h0[N_NODES * H];
__device__ __align__(16) float g_h [N_NODES * H];
__device__ float g_deg[N_NODES];
__device__ float g_A[N_NODES];
__device__ float g_B[N_NODES];
__device__ float g_efeat[N_EDGES * C_EF];
__device__ __align__(16) float g_Wre[H * C_W * H];        // [i][c][o]
__device__ __align__(16) float g_T  [N_NODES * C_W * H];  // [n][c][o]
__device__ __align__(16) float g_agg[N_NODES * H];
__device__ __align__(16) float g_feat[N_NODES * D2];
// packed weights
__device__ __align__(16) float g_WpT [NODE_IN * H];        // [i][o]
__device__ __align__(16) float g_gw8 [H * H * 8];          // [i][o][{wr,wz,wn,0,vr,vz,vn,0}]
__device__ __align__(16) float g_lw4 [2 * D2 * 4 * D2];    // [i][d][gate]   256x128x4
__device__ __align__(16) float g_lh4 [D2 * 4 * D2];        // [i][d][gate]   128x128x4
__device__ __align__(16) float g_Ws8 [2 * D2 * RD];        // [i][d][k]      256x128x8

__device__ __forceinline__ float sigf(float x) { return 1.0f / (1.0f + expf(-x)); }

__device__ __forceinline__ u64 pk2(float a, float b) {
    u64 r; asm("mov.b64 %0, {%1, %2};" : "=l"(r) : "f"(a), "f"(b)); return r;
}
__device__ __forceinline__ void unpk2(u64 v, float& a, float& b) {
    asm("mov.b64 {%0, %1}, %2;" : "=f"(a), "=f"(b) : "l"(v));
}
__device__ __forceinline__ u64 ffma2(u64 a, u64 b, u64 c) {
    u64 d; asm("fma.rn.f32x2 %0, %1, %2, %3;" : "=l"(d) : "l"(a), "l"(b), "l"(c)); return d;
}

// ---------------- prep ------------------------------------------------------
#define S_WPT   (NODE_IN * H)         // 4736
#define S_GW8   (H * H * 8)           // 32768
#define S_LW4   (2 * D2 * 4 * D2)     // 131072
#define S_LH4   (D2 * 4 * D2)         // 65536
#define S_WS8   (2 * D2 * RD)         // 262144
#define S_WRE   (H * C_W * H)         // 57344
#define PREP_TOTAL (S_WPT + S_GW8 + S_LW4 + S_LH4 + S_WS8 + S_WRE + N_NODES + N_NODES*H)

__global__ void prep_kernel(const float* __restrict__ Wp,
                            const float* __restrict__ gwih,
                            const float* __restrict__ gwhh,
                            const float* __restrict__ lwih,
                            const float* __restrict__ lwhh,
                            const float* __restrict__ Ws,
                            const float* __restrict__ We,
                            const float* __restrict__ be) {
    int idx = blockIdx.x * blockDim.x + threadIdx.x;
    if (idx < S_WPT) {
        int i = idx / H, o = idx % H;
        g_WpT[idx] = Wp[o * NODE_IN + i]; return;
    }
    idx -= S_WPT;
    if (idx < S_GW8) {
        int i = idx / 512, rest = idx % 512, o = rest / 8, k = rest % 8;
        float v = 0.0f;
        if (k < 3)              v = gwih[(k * H + o) * H + i];
        else if (k >= 4 && k < 7) v = gwhh[((k - 4) * H + o) * H + i];
        g_gw8[idx] = v; return;
    }
    idx -= S_GW8;
    if (idx < S_LW4) {
        int i = idx / 512, rest = idx % 512, d = rest / 4, k = rest % 4;
        g_lw4[idx] = lwih[(k * D2 + d) * 256 + i]; return;
    }
    idx -= S_LW4;
    if (idx < S_LH4) {
        int i = idx / 512, rest = idx % 512, d = rest / 4, k = rest % 4;
        g_lh4[idx] = lwhh[(k * D2 + d) * D2 + i]; return;
    }
    idx -= S_LH4;
    if (idx < S_WS8) {
        int i = idx / RD, rest = idx % RD, d = rest / 8, k = rest % 8;
        g_Ws8[idx] = Ws[(k * D2 + d) * 256 + i]; return;
    }
    idx -= S_WS8;
    if (idx < S_WRE) {
        int i = idx / (C_W * H);
        int r = idx % (C_W * H);
        int c = r / H, o = r % H;
        g_Wre[idx] = (c < C_EF) ? We[(i * H + o) * C_EF + c] : be[i * H + o];
        return;
    }
    idx -= S_WRE;
    if (idx < N_NODES) { g_deg[idx] = 0.0f; return; }
    idx -= N_NODES;
    if (idx < N_NODES * H) g_agg[idx] = 0.0f;
}

// ---------------- projection + per-node gate dots + degree counting ---------
#define PROJ_BLKS (N_NODES / 16)              // 625, 16 nodes per 128-thread block
#define DEG_BLKS  ((N_EDGES + 127) / 128)     // 313

__global__ __launch_bounds__(128) void projdeg_kernel(const float* __restrict__ na,
                                                      const float* __restrict__ bp,
                                                      const float* __restrict__ Wg,
                                                      const int* __restrict__ dstv) {
    if (blockIdx.x >= PROJ_BLKS) {
        int e = (blockIdx.x - PROJ_BLKS) * 128 + threadIdx.x;
        if (e < N_EDGES) atomicAdd(&g_deg[dstv[e]], 1.0f);
        return;
    }
    int grp = threadIdx.x >> 6;               // 0/1
    int o   = threadIdx.x & 63;
    int n0  = blockIdx.x * 16 + grp * NB;
    __shared__ __align__(16) float xs[NODE_IN][16];
    __shared__ float red[2][2][16];
    for (int idx = threadIdx.x; idx < 16 * NODE_IN; idx += 128) {
        int t = idx / NODE_IN, i = idx % NODE_IN;
        xs[i][t] = na[(blockIdx.x * 16 + t) * NODE_IN + i];
    }
    __syncthreads();
    u64 acc[NB / 2];
    float b = bp[o];
    u64 b2 = pk2(b, b);
#pragma unroll
    for (int j = 0; j < NB / 2; j++) acc[j] = b2;
    for (int i = 0; i < NODE_IN; i++) {
        float w = g_WpT[i * H + o];
        u64 wp = pk2(w, w);
        const ulonglong2* xp = (const ulonglong2*)&xs[i][grp * NB];
#pragma unroll
        for (int j = 0; j < NB / 4; j++) {
            ulonglong2 v = xp[j];
            acc[2 * j]     = ffma2(v.x, wp, acc[2 * j]);
            acc[2 * j + 1] = ffma2(v.y, wp, acc[2 * j + 1]);
        }
    }
    float v[NB];
#pragma unroll
    for (int j = 0; j < NB / 2; j++) {
        float a, c; unpk2(acc[j], a, c);
        v[2 * j] = fmaxf(a, 0.0f);
        v[2 * j + 1] = fmaxf(c, 0.0f);
        g_h0[(n0 + 2 * j) * H + o] = v[2 * j];  g_h[(n0 + 2 * j) * H + o] = v[2 * j];
        g_h0[(n0 + 2 * j + 1) * H + o] = v[2 * j + 1]; g_h[(n0 + 2 * j + 1) * H + o] = v[2 * j + 1];
    }
    // A[n] = Wg[0:64]·h0[n], B[n] = Wg[64:128]·h0[n]
    float wA = Wg[o], wB = Wg[64 + o];
    int wg = (threadIdx.x >> 5) & 1, lane = threadIdx.x & 31;
#pragma unroll
    for (int t = 0; t < NB; t++) {
        float a = wA * v[t], bb = wB * v[t];
#pragma unroll
        for (int off = 16; off; off >>= 1) {
            a  += __shfl_xor_sync(0xffffffffu, a, off);
            bb += __shfl_xor_sync(0xffffffffu, bb, off);
        }
        if (lane == 0) { red[grp][wg][2 * t] = a; red[grp][wg][2 * t + 1] = bb; }
    }
    __syncthreads();
    if (threadIdx.x < 32) {
        int gr = threadIdx.x >> 4, sub = threadIdx.x & 15;
        int t = sub >> 1, isB = sub & 1;
        float val = red[gr][0][sub] + red[gr][1][sub];
        int n = blockIdx.x * 16 + gr * NB + t;
        if (isB) g_B[n] = val; else g_A[n] = val;
    }
}

// ---------------- T = h @ Wre, optionally fused with gate -------------------
#define T_BLKS  ((N_NODES / TNB) * (C_W / 2))   // 1750
#define GATE_BLKS (N_EDGES / 64)                // 625

__global__ __launch_bounds__(H) void t_kernel(const float* __restrict__ ea,
                                              const int* __restrict__ src,
                                              const int* __restrict__ dstv,
                                              const float* __restrict__ bg) {
    if (blockIdx.x >= T_BLKS) {                 // gate part (step 0 only)
        int e = (blockIdx.x - T_BLKS) * 64 + threadIdx.x;
        int s = src[e], d = dstv[e];
        float t = tanhf(g_A[d] + g_B[s] + bg[0]);
        float eg = 0.3f + t * g_deg[d] * g_deg[s];
#pragma unroll
        for (int i = 0; i < EDGE_IN; i++) g_efeat[e * C_EF + i] = ea[e * EDGE_IN + i];
        g_efeat[e * C_EF + 12] = eg;
        return;
    }
    int c0 = (blockIdx.x / 250) * 2;
    int n0 = (blockIdx.x % 250) * TNB;
    int o  = threadIdx.x;
    __shared__ __align__(16) float hs2[H][44];
    for (int t = 0; t < TNB; t++) hs2[o][t] = g_h[(n0 + t) * H + o];
    __syncthreads();
    u64 a0[TNB / 2], a1[TNB / 2];
    u64 z = pk2(0.0f, 0.0f);
#pragma unroll
    for (int j = 0; j < TNB / 2; j++) { a0[j] = z; a1[j] = z; }
    const float* w0p = g_Wre + c0 * H + o;
    const float* w1p = g_Wre + (c0 + 1) * H + o;
    for (int i = 0; i < H; i++) {
        float w0 = w0p[i * (C_W * H)];
        float w1 = w1p[i * (C_W * H)];
        u64 wp0 = pk2(w0, w0), wp1 = pk2(w1, w1);
        const ulonglong2* hp = (const ulonglong2*)hs2[i];
#pragma unroll
        for (int j = 0; j < TNB / 4; j++) {
            ulonglong2 v = hp[j];
            a0[2 * j]     = ffma2(v.x, wp0, a0[2 * j]);
            a0[2 * j + 1] = ffma2(v.y, wp0, a0[2 * j + 1]);
            a1[2 * j]     = ffma2(v.x, wp1, a1[2 * j]);
            a1[2 * j + 1] = ffma2(v.y, wp1, a1[2 * j + 1]);
        }
    }
#pragma unroll
    for (int j = 0; j < TNB / 2; j++) {
        float x, y;
        unpk2(a0[j], x, y);
        g_T[(size_t)(n0 + 2 * j) * (C_W * H) + c0 * H + o]     = x;
        g_T[(size_t)(n0 + 2 * j + 1) * (C_W * H) + c0 * H + o] = y;
        unpk2(a1[j], x, y);
        g_T[(size_t)(n0 + 2 * j) * (C_W * H) + (c0 + 1) * H + o]     = x;
        g_T[(size_t)(n0 + 2 * j + 1) * (C_W * H) + (c0 + 1) * H + o] = y;
    }
}

// ---------------- edge messages (4 edges / 256-thread block) ----------------
__global__ __launch_bounds__(256) void msg_kernel(const int* __restrict__ src,
                                                  const int* __restrict__ dstv) {
    int sub = threadIdx.x >> 6;
    int o   = threadIdx.x & 63;
    int e   = blockIdx.x * 4 + sub;
    __shared__ float ef[4][C_EF];
    if (o < C_EF) ef[sub][o] = g_efeat[e * C_EF + o];
    __syncthreads();
    int s = src[e], d = dstv[e];
    const float* Ts = g_T + (size_t)s * (C_W * H);
    float acc = __ldg(&Ts[C_EF * H + o]);
#pragma unroll
    for (int c = 0; c < C_EF; c++) acc = fmaf(ef[sub][c], __ldg(&Ts[c * H + o]), acc);
    atomicAdd(&g_agg[d * H + o], acc);
}

// ---------------- GRU (f32x2, zeroes agg, writes feat on last step) ---------
__global__ __launch_bounds__(H) void gru_kernel(const float* __restrict__ bih,
                                                const float* __restrict__ bhh,
                                                const float* __restrict__ ncb,
                                                int last) {
    int n0 = blockIdx.x * NB;
    int o  = threadIdx.x;
    __shared__ __align__(16) float xs2[H][NB], hs2[H][NB];
    float nb = ncb[o];
#pragma unroll
    for (int t = 0; t < NB; t++) {
        int a = (n0 + t) * H + o;
        xs2[o][t] = fmaxf(g_agg[a] + nb, 0.0f);
        g_agg[a] = 0.0f;
        hs2[o][t] = g_h[a];
    }
    __syncthreads();
    u64 aR[NB/2], aZ[NB/2], aN[NB/2], cR[NB/2], cZ[NB/2], cN[NB/2];
    u64 z = pk2(0.0f, 0.0f);
#pragma unroll
    for (int j = 0; j < NB/2; j++) { aR[j]=aZ[j]=aN[j]=cR[j]=cZ[j]=cN[j]=z; }
    for (int i = 0; i < H; i++) {
        const float4* wp4 = (const float4*)&g_gw8[i * 512 + o * 8];
        float4 wv = wp4[0];          // wr, wz, wn, pad
        float4 vv = wp4[1];          // vr, vz, vn, pad
        u64 wr2 = pk2(wv.x, wv.x), wz2 = pk2(wv.y, wv.y), wn2 = pk2(wv.z, wv.z);
        u64 vr2 = pk2(vv.x, vv.x), vz2 = pk2(vv.y, vv.y), vn2 = pk2(vv.z, vv.z);
        const ulonglong2* xp = (const ulonglong2*)xs2[i];
        const ulonglong2* hp = (const ulonglong2*)hs2[i];
#pragma unroll
        for (int j = 0; j < NB / 4; j++) {
            ulonglong2 xv = xp[j], hv = hp[j];
            aR[2*j]   = ffma2(xv.x, wr2, aR[2*j]);   aR[2*j+1] = ffma2(xv.y, wr2, aR[2*j+1]);
            aZ[2*j]   = ffma2(xv.x, wz2, aZ[2*j]);   aZ[2*j+1] = ffma2(xv.y, wz2, aZ[2*j+1]);
            aN[2*j]   = ffma2(xv.x, wn2, aN[2*j]);   aN[2*j+1] = ffma2(xv.y, wn2, aN[2*j+1]);
            cR[2*j]   = ffma2(hv.x, vr2, cR[2*j]);   cR[2*j+1] = ffma2(hv.y, vr2, cR[2*j+1]);
            cZ[2*j]   = ffma2(hv.x, vz2, cZ[2*j]);   cZ[2*j+1] = ffma2(hv.y, vz2, cZ[2*j+1]);
            cN[2*j]   = ffma2(hv.x, vn2, cN[2*j]);   cN[2*j+1] = ffma2(hv.y, vn2, cN[2*j+1]);
        }
    }
    float biR = bih[o], biZ = bih[H + o], biN = bih[2 * H + o];
    float bhR = bhh[o], bhZ = bhh[H + o], bhN = bhh[2 * H + o];
#pragma unroll
    for (int j = 0; j < NB / 2; j++) {
        float ar0, ar1, az0, az1, an0, an1, cr0, cr1, cz0, cz1, cn0, cn1;
        unpk2(aR[j], ar0, ar1); unpk2(aZ[j], az0, az1); unpk2(aN[j], an0, an1);
        unpk2(cR[j], cr0, cr1); unpk2(cZ[j], cz0, cz1); unpk2(cN[j], cn0, cn1);
#pragma unroll
        for (int k = 0; k < 2; k++) {
            int t = 2 * j + k;
            float ar = k ? ar1 : ar0, az = k ? az1 : az0, an = k ? an1 : an0;
            float cr = k ? cr1 : cr0, cz = k ? cz1 : cz0, cn = k ? cn1 : cn0;
            float r  = sigf(ar + biR + cr + bhR);
            float zz = sigf(az + biZ + cz + bhZ);
            float ng = tanhf(an + biN + r * (cn + bhN));
            float hold = hs2[o][t];
            float hnew = (1.0f - zz) * ng + zz * hold;
            int a = (n0 + t) * H + o;
            g_h[a] = hnew;
            if (last) {
                g_feat[(n0 + t) * D2 + H + o] = hnew;
                g_feat[(n0 + t) * D2 + o]     = g_h0[a];
            }
        }
    }
}

// ---------------- fused Set2Set (3 steps) + output linear -------------------
// 50 blocks x 640 threads; group g = tid/128 owns graph b0+g; d = tid%128.
// dyn smem: fs[5][40*128] + hl[5][128] + cl[5][128] + qs[5][256] + sc/ex[5][40]
#define SM_FS   0
#define SM_HL   (LG * NODES_PG * D2)                 // 25600
#define SM_CL   (SM_HL + LG * D2)                    // +640
#define SM_QS   (SM_CL + LG * D2)                    // +640
#define SM_SC   (SM_QS + LG * 2 * D2)                // +1280
#define SM_EX   (SM_SC + LG * NODES_PG)              // +200
#define SM_TOT  (SM_EX + LG * NODES_PG)              // +200 = 28560 floats

__global__ __launch_bounds__(LG * D2, 1) void s2s_kernel(const float* __restrict__ bih,
                                                         const float* __restrict__ bhh,
                                                         const float* __restrict__ bs,
                                                         const float* __restrict__ prelu_a,
                                                         float* __restrict__ out) {
    extern __shared__ float sm[];
    int tid = threadIdx.x;
    int g = tid >> 7, d = tid & 127;
    int b0 = blockIdx.x * LG;
    float* fs  = sm + SM_FS + g * (NODES_PG * D2);
    float* hls = sm + SM_HL + g * D2;
    float* cls = sm + SM_CL + g * D2;
    float* qs  = sm + SM_QS + g * (2 * D2);
    float* sc  = sm + SM_SC + g * NODES_PG;
    float* ex  = sm + SM_EX + g * NODES_PG;

#pragma unroll
    for (int t = 0; t < NODES_PG; t++)
        fs[t * D2 + d] = g_feat[(size_t)((b0 + g) * NODES_PG + t) * D2 + d];
    hls[d] = 0.0f; cls[d] = 0.0f;
    qs[d] = 0.0f; qs[D2 + d] = 0.0f;
    __syncthreads();

    float bI = bih[d] + bhh[d];
    float bF = bih[D2 + d] + bhh[D2 + d];
    float bG = bih[2 * D2 + d] + bhh[2 * D2 + d];
    float bO = bih[3 * D2 + d] + bhh[3 * D2 + d];

    for (int step = 0; step < 3; step++) {
        float aI = bI, aF = bF, aG = bG, aO = bO;
        if (step > 0) {
#pragma unroll 4
            for (int i = 0; i < 2 * D2; i++) {
                float q = qs[i];
                float4 w = *(const float4*)&g_lw4[i * 512 + d * 4];
                aI = fmaf(q, w.x, aI); aF = fmaf(q, w.y, aF);
                aG = fmaf(q, w.z, aG); aO = fmaf(q, w.w, aO);
            }
#pragma unroll 4
            for (int i = 0; i < D2; i++) {
                float hh = hls[i];
                float4 w = *(const float4*)&g_lh4[i * 512 + d * 4];
                aI = fmaf(hh, w.x, aI); aF = fmaf(hh, w.y, aF);
                aG = fmaf(hh, w.z, aG); aO = fmaf(hh, w.w, aO);
            }
        }
        float I = sigf(aI), F = sigf(aF), G = tanhf(aG), O = sigf(aO);
        float c = F * cls[d] + I * G;
        cls[d] = c;
        float hv = O * tanhf(c);
        hls[d] = hv;
        __syncthreads();
        // scores: 4 warps per group round-robin over 40 nodes
        int w4 = (d >> 5), lane = d & 31;
        for (int t = w4; t < NODES_PG; t += 4) {
            const float* fr = fs + t * D2;
            float a = fr[lane]      * hls[lane]
                    + fr[32 + lane] * hls[32 + lane]
                    + fr[64 + lane] * hls[64 + lane]
                    + fr[96 + lane] * hls[96 + lane];
#pragma unroll
            for (int off = 16; off; off >>= 1) a += __shfl_xor_sync(0xffffffffu, a, off);
            if (lane == 0) sc[t] = a;
        }
        __syncthreads();
        float mx = -1e30f;
#pragma unroll
        for (int t = 0; t < NODES_PG; t++) mx = fmaxf(mx, sc[t]);
        if (d < NODES_PG) ex[d] = expf(sc[d] - mx);
        __syncthreads();
        float den = 0.0f;
#pragma unroll
        for (int t = 0; t < NODES_PG; t++) den += ex[t];
        float racc = 0.0f;
#pragma unroll
        for (int t = 0; t < NODES_PG; t++) racc = fmaf(fs[t * D2 + d], ex[t], racc);
        racc /= den;
        qs[d] = hv;
        qs[D2 + d] = racc;
        __syncthreads();
    }
    // output: r = k*128 + d, k = 0..7
    float acc[8];
#pragma unroll
    for (int k = 0; k < 8; k++) acc[k] = bs[k * D2 + d];
#pragma unroll 2
    for (int i = 0; i < 2 * D2; i++) {
        float q = qs[i];
        const float4* wp = (const float4*)&g_Ws8[i * RD + d * 8];
        float4 w0 = wp[0], w1 = wp[1];
        acc[0] = fmaf(q, w0.x, acc[0]); acc[1] = fmaf(q, w0.y, acc[1]);
        acc[2] = fmaf(q, w0.z, acc[2]); acc[3] = fmaf(q, w0.w, acc[3]);
        acc[4] = fmaf(q, w1.x, acc[4]); acc[5] = fmaf(q, w1.y, acc[5]);
        acc[6] = fmaf(q, w1.z, acc[6]); acc[7] = fmaf(q, w1.w, acc[7]);
    }
    float pa = prelu_a[0];
#pragma unroll
    for (int k = 0; k < 8; k++) {
        float v = acc[k];
        out[(size_t)(b0 + g) * RD + k * D2 + d] = (v >= 0.0f) ? v : pa * v;
    }
}

// ============================================================================
extern "C" void kernel_launch(void* const* d_in, const int* in_sizes, int n_in,
                              void* d_out, int out_size) {
    const float* node_attr = (const float*)d_in[0];
    const float* edge_attr = (const float*)d_in[1];
    const int*   src       = (const int*)d_in[2];
    const int*   dst       = (const int*)d_in[3];
    const float* Wp   = (const float*)d_in[6];
    const float* bp   = (const float*)d_in[7];
    const float* Wg   = (const float*)d_in[8];
    const float* bg   = (const float*)d_in[9];
    const float* We   = (const float*)d_in[10];
    const float* be   = (const float*)d_in[11];
    const float* ncb  = (const float*)d_in[12];
    const float* gbih = (const float*)d_in[15];
    const float* gbhh = (const float*)d_in[16];
    const float* lbih = (const float*)d_in[19];
    const float* lbhh = (const float*)d_in[20];
    const float* bs   = (const float*)d_in[22];
    const float* pa   = (const float*)d_in[23];
    float* out = (float*)d_out;

    static int s2s_attr_set = 0;
    if (!s2s_attr_set) {
        cudaFuncSetAttribute(s2s_kernel, cudaFuncAttributeMaxDynamicSharedMemorySize,
                             SM_TOT * (int)sizeof(float));
        s2s_attr_set = 1;
    }

    prep_kernel<<<(PREP_TOTAL + 255) / 256, 256>>>(
        Wp, (const float*)d_in[13], (const float*)d_in[14],
        (const float*)d_in[17], (const float*)d_in[18],
        (const float*)d_in[21], We, be);

    projdeg_kernel<<<PROJ_BLKS + DEG_BLKS, 128>>>(node_attr, bp, Wg, dst);

    for (int step = 0; step < 3; step++) {
        int tb = (step == 0) ? (T_BLKS + GATE_BLKS) : T_BLKS;
        t_kernel<<<tb, H>>>(edge_attr, src, dst, bg);
        msg_kernel<<<N_EDGES / 4, 256>>>(src, dst);
        gru_kernel<<<N_NODES / NB, H>>>(gbih, gbhh, ncb, step == 2);
    }

    s2s_kernel<<<N_GRAPHS / LG, LG * D2, SM_TOT * (int)sizeof(float)>>>(
        lbih, lbhh, bs, pa, out);
}